// round 10
// baseline (speedup 1.0000x reference)
#include <cuda_runtime.h>
#include <math.h>

// ---------------------------------------------------------------------------
// HyperNetworkDecoder: K=2, P=4096, 8 layers of width 64.
// hyper_kernel: generate per-(k,layer) weights once, transposed [m][n].
// decode_kernel: n-packed fp32x2 — accumulator u64 = (y[n], y[n+1]) for ONE
// point, so weight packs come straight from smem LDS.128 (no MOVs) and x is
// stored DUPLICATED in smem so the x operand is one broadcast LDS.64.
// Thread = (point, n-group of 8 outputs); warp = 4 points x 8 n-groups.
// ---------------------------------------------------------------------------

#define KB 2
typedef unsigned long long u64;

__device__ __align__(16) float g_W0[KB * 128 * 64];      // layer0 W^T [k][m pad128][n]
__device__ __align__(16) float g_Wl[KB * 7 * 64 * 64];   // layers 1..7 W^T [k][l-1][m][n]
__device__ __align__(16) float g_b [KB * 8 * 64];        // biases [k][l][n]

// ---------------------------------------------------------------------------
// Kernel 1: hypernetwork (unchanged). grid = (k,l) x 16 splits = 256 blocks.
// ---------------------------------------------------------------------------
__global__ void __launch_bounds__(512) hyper_kernel(
    const float* __restrict__ latent_tokens,
    const float* __restrict__ token_embeddings,
    const float* __restrict__ h_W0,  const float* __restrict__ h_b0,
    const float* __restrict__ h_ln_s0, const float* __restrict__ h_ln_b0,
    const float* __restrict__ w_W0,  const float* __restrict__ w_b0,
    const float* __restrict__ bb_W0, const float* __restrict__ bb_b0,
    const float* __restrict__ h_W,   const float* __restrict__ h_b,
    const float* __restrict__ h_ln_s, const float* __restrict__ h_ln_b,
    const float* __restrict__ w_W,   const float* __restrict__ w_b,
    const float* __restrict__ bb_W,  const float* __restrict__ bb_b)
{
    __shared__ float chunk[128];
    __shared__ float part[4][64];
    __shared__ float pre[64];
    __shared__ float hbuf[64];
    __shared__ float wpart[1024];

    const int tid = threadIdx.x;
    const int bx  = blockIdx.x;
    const int sp  = bx & 15;
    const int kl  = bx >> 4;
    const int k   = kl >> 3;
    const int l   = kl & 7;

    if (tid < 128)
        chunk[tid] = (tid < 64) ? latent_tokens[(k * 8 + l) * 64 + tid]
                                : token_embeddings[l * 64 + (tid - 64)];
    __syncthreads();

    const float* hWp = (l == 0) ? h_W0 : (h_W + (l - 1) * 128 * 64);
    if (tid < 256) {
        const int q = tid >> 6, j = tid & 63;
        float acc = 0.f;
        #pragma unroll
        for (int i = 0; i < 32; i++) {
            int ii = q * 32 + i;
            acc = fmaf(chunk[ii], __ldg(hWp + ii * 64 + j), acc);
        }
        part[q][j] = acc;
    }
    __syncthreads();
    if (tid < 64) {
        float hb = (l == 0) ? __ldg(h_b0 + tid) : __ldg(h_b + (l - 1) * 64 + tid);
        pre[tid] = part[0][tid] + part[1][tid] + part[2][tid] + part[3][tid] + hb;
    }
    __syncthreads();
    if (tid < 64) {
        float s1 = 0.f, s2 = 0.f;
        #pragma unroll 8
        for (int i = 0; i < 64; i++) { float v = pre[i]; s1 += v; s2 += v * v; }
        float mu   = s1 * (1.f / 64.f);
        float var  = s2 * (1.f / 64.f) - mu * mu;
        float rstd = rsqrtf(var + 1e-6f);
        float ls = (l == 0) ? __ldg(h_ln_s0 + tid) : __ldg(h_ln_s + (l - 1) * 64 + tid);
        float lb = (l == 0) ? __ldg(h_ln_b0 + tid) : __ldg(h_ln_b + (l - 1) * 64 + tid);
        float h  = fmaf((pre[tid] - mu) * rstd, ls, lb);
        hbuf[tid] = fmaxf(h, 0.f);
    }
    __syncthreads();

    const int OUT  = (l == 0) ? 8064 : 4096;
    const int CH   = OUT >> 4;
    const int o0   = sp * CH, oend = o0 + CH;
    const float* wWp = (l == 0) ? w_W0 : (w_W + (l - 1) * 64 * 4096);
    const float* wbp = (l == 0) ? w_b0 : (w_b + (l - 1) * 4096);

    const int g  = tid >> 8;
    const int tt = tid & 255;

    float acc[2];
    #pragma unroll
    for (int i = 0; i < 2; i++) {
        int o = o0 + tt + i * 256;
        acc[i] = (o < oend && g == 0) ? __ldg(wbp + o) : 0.f;
    }
    const int j0 = g * 32;
    #pragma unroll 8
    for (int jj = 0; jj < 32; jj++) {
        float hj = hbuf[j0 + jj];
        const float* row = wWp + (j0 + jj) * OUT;
        #pragma unroll
        for (int i = 0; i < 2; i++) {
            int o = o0 + tt + i * 256;
            if (o < oend) acc[i] = fmaf(hj, __ldg(row + o), acc[i]);
        }
    }
    wpart[g * 512 + tt]       = acc[0];
    wpart[g * 512 + 256 + tt] = acc[1];
    __syncthreads();

    if (g == 0) {
        #pragma unroll
        for (int i = 0; i < 2; i++) {
            int o = o0 + tt + i * 256;
            if (o < oend) {
                float v = acc[i] + wpart[512 + i * 256 + tt];
                if (l == 0) {
                    int n = o / 126, m = o - n * 126;
                    g_W0[k * 8192 + m * 64 + n] = v;
                } else {
                    int n = o >> 6, m = o & 63;
                    g_Wl[k * 28672 + (l - 1) * 4096 + m * 64 + n] = v;
                }
            }
        }
    }

    if (sp == 0) {
        if (l == 0 && tid < 128)
            g_W0[k * 8192 + 8064 + tid] = 0.f;
        if (tid < 64) {
            const float* bWp = (l == 0) ? bb_W0 : (bb_W + (l - 1) * 64 * 64);
            float accb = (l == 0) ? __ldg(bb_b0 + tid) : __ldg(bb_b + (l - 1) * 64 + tid);
            #pragma unroll 8
            for (int j = 0; j < 64; j++)
                accb = fmaf(hbuf[j], __ldg(bWp + j * 64 + tid), accb);
            g_b[(k * 8 + l) * 64 + tid] = accb;
        }
    }
}

// ---------------------------------------------------------------------------
// Packed fp32 (f32x2) primitives.
// ---------------------------------------------------------------------------
#define FMA2(D, A, B, C) asm("fma.rn.f32x2 %0, %1, %2, %3;" : "=l"(D) : "l"(A), "l"(B), "l"(C))
#define ADD2(D, A, B)    asm("add.rn.f32x2 %0, %1, %2;"     : "=l"(D) : "l"(A), "l"(B))
#define MUL2(D, A, B)    asm("mul.rn.f32x2 %0, %1, %2;"     : "=l"(D) : "l"(A), "l"(B))

__device__ __forceinline__ u64 pk2(float lo, float hi)
{ u64 d; asm("mov.b64 %0, {%1,%2};" : "=l"(d) : "f"(lo), "f"(hi)); return d; }
__device__ __forceinline__ void upk2(float& lo, float& hi, u64 s)
{ asm("mov.b64 {%0,%1}, %2;" : "=f"(lo), "=f"(hi) : "l"(s)); }

// ---------------------------------------------------------------------------
// Float-only accurate sin: 2-term Cody-Waite reduction by pi, then sinf.
// ---------------------------------------------------------------------------
__device__ __forceinline__ float acc_sin(float x)
{
    float q = rintf(x * 0.318309886183790672f);
    float r = fmaf(-q, 3.14159274101257324f, x);
    r = fmaf(-q, -8.74227800037e-8f, r);
    float s = sinf(r);
    return (((int)q) & 1) ? -s : s;
}

// ---------------------------------------------------------------------------
// Kernel 2: decoder. 128 blocks x 512 threads, 64 points/block (one k).
// Warp wp: 4 points (pt = lane>>3), 8 n-groups (ng = lane&7). Thread owns
// outputs n in {4ng..4ng+3} u {32+4ng..32+4ng+3} as 4 n-packed u64 accs.
// x stored duplicated (u64 per element, row stride 133 u64 -> conflict-free).
// ---------------------------------------------------------------------------
#define XSTRIDE 133

__global__ void __launch_bounds__(512, 1) decode_kernel(
    const float* __restrict__ rays,
    const float* __restrict__ ln_s0, const float* __restrict__ ln_b0,
    const float* __restrict__ ln_s,  const float* __restrict__ ln_b,
    const float* __restrict__ rgb_W, const float* __restrict__ rgb_b,
    float* __restrict__ out)
{
    extern __shared__ float smem[];
    float4* sW  = (float4*)smem;            // 9216 float4: W0 (2048) + Wl (7168)
    u64*    xs  = (u64*)(sW + 9216);        // 64 pts * 133 u64 (duplicated x)

    const int tid  = threadIdx.x;
    const int wp   = tid >> 5;
    const int lane = tid & 31;
    const int pt   = lane >> 3;             // point in warp 0..3
    const int ng   = lane & 7;              // n-group 0..7
    const int k    = blockIdx.x >> 6;
    const int P    = 4 * wp + pt;           // point in block 0..63
    const int gpt  = blockIdx.x * 64 + P;

    u64* xrow = xs + P * XSTRIDE;

    // ---- weight load (coalesced, 18 float4 per thread) ----
    {
        const float4* s0 = (const float4*)g_W0 + k * 2048;
        const float4* s1 = (const float4*)g_Wl + k * 7168;
        #pragma unroll
        for (int i = 0; i < 4; i++)  sW[tid + i * 512] = __ldg(s0 + tid + i * 512);
        #pragma unroll
        for (int i = 0; i < 14; i++) sW[2048 + tid + i * 512] = __ldg(s1 + tid + i * 512);
    }

    // ---- positional encoding (8 lanes per point, duplicated u64 writes) ----
    {
        const float* r = rays + gpt * 6;
        float ox = __ldg(r + 0), oy = __ldg(r + 1), oz = __ldg(r + 2);
        float dx = __ldg(r + 3), dy = __ldg(r + 4), dz = __ldg(r + 5);
        float pl[6];
        pl[0] = dx; pl[1] = dy; pl[2] = dz;
        pl[3] = oy * dz - oz * dy;
        pl[4] = oz * dx - ox * dz;
        pl[5] = ox * dy - oy * dx;
        if (ng == 6) {
            #pragma unroll
            for (int cm = 0; cm < 6; cm++) xrow[cm] = pk2(pl[cm], pl[cm]);
        }
        if (ng == 7) { xrow[126] = 0ull; xrow[127] = 0ull; }
        const float PIH = 1.57079632679489662f;
        for (int f = ng; f < 10; f += 8) {
            float fr = (float)(1 << f);
            #pragma unroll
            for (int cm = 0; cm < 6; cm++) {
                float a  = pl[cm] * fr;
                float sv = acc_sin(a);
                float cv = acc_sin(a + PIH);
                xrow[6 + f * 6 + cm]  = pk2(sv, sv);
                xrow[66 + f * 6 + cm] = pk2(cv, cv);
            }
        }
    }
    __syncthreads();   // the ONLY block barrier

    const float* bb = g_b + k * 512;
    const int nlo = 4 * ng;                 // first n of low group
    u64 a0, a1, a2, a3;                     // (y[nlo],y[nlo+1]) (y[nlo+2],y[nlo+3])
                                            // (y[nlo+32],...) (y[nlo+34],...)

    #pragma unroll 1
    for (int l = 0; l < 8; l++) {
        const ulonglong2* Wt = (l == 0) ? (const ulonglong2*)sW
                                        : (const ulonglong2*)(sW + 2048 + (l - 1) * 1024);
        const int M = (l == 0) ? 128 : 64;

        {   // bias init: n-contiguous -> direct packed loads
            ulonglong2 ba = __ldg((const ulonglong2*)(bb + l * 64 + nlo));
            ulonglong2 bb2 = __ldg((const ulonglong2*)(bb + l * 64 + 32 + nlo));
            a0 = ba.x;  a1 = ba.y;
            a2 = bb2.x; a3 = bb2.y;
        }

        #pragma unroll 8
        for (int m = 0; m < M; m++) {
            // row m = 16 ulonglong2; [m][nlo..nlo+3] and [m][nlo+32..+35]
            ulonglong2 wa = Wt[m * 16 + ng];
            ulonglong2 wb = Wt[m * 16 + 8 + ng];
            u64 x = xrow[m];                        // broadcast (x, x)
            FMA2(a0, x, wa.x, a0);
            FMA2(a1, x, wa.y, a1);
            FMA2(a2, x, wb.x, a2);
            FMA2(a3, x, wb.y, a3);
        }

        // ---- LayerNorm + relu ----
        u64 s1u = a0;
        ADD2(s1u, s1u, a1);
        ADD2(s1u, s1u, a2);
        ADD2(s1u, s1u, a3);
        u64 s2u = 0ull;
        FMA2(s2u, a0, a0, s2u);
        FMA2(s2u, a1, a1, s2u);
        FMA2(s2u, a2, a2, s2u);
        FMA2(s2u, a3, a3, s2u);
        float t1a, t1b, t2a, t2b;
        upk2(t1a, t1b, s1u);
        upk2(t2a, t2b, s2u);
        float s1 = t1a + t1b, s2 = t2a + t2b;
        #pragma unroll
        for (int mm = 1; mm < 8; mm <<= 1) {
            s1 += __shfl_xor_sync(0xffffffffu, s1, mm, 32);
            s2 += __shfl_xor_sync(0xffffffffu, s2, mm, 32);
        }
        float mu = s1 * (1.f / 64.f);
        float rs = rsqrtf(s2 * (1.f / 64.f) - mu * mu + 1e-6f);
        u64 nmu = pk2(-mu, -mu);
        u64 rsd = pk2(rs, rs);

        const float* lns = (l == 0) ? ln_s0 : (ln_s + (l - 1) * 64);
        const float* lnb = (l == 0) ? ln_b0 : (ln_b + (l - 1) * 64);
        ulonglong2 lsa = __ldg((const ulonglong2*)(lns + nlo));
        ulonglong2 lsb = __ldg((const ulonglong2*)(lns + 32 + nlo));
        ulonglong2 lba = __ldg((const ulonglong2*)(lnb + nlo));
        ulonglong2 lbb = __ldg((const ulonglong2*)(lnb + 32 + nlo));

        u64 av[4] = { a0, a1, a2, a3 };
        u64 lsv[4] = { lsa.x, lsa.y, lsb.x, lsb.y };
        u64 lbv[4] = { lba.x, lba.y, lbb.x, lbb.y };
        const int nn[4] = { nlo, nlo + 2, nlo + 32, nlo + 34 };

        #pragma unroll
        for (int j = 0; j < 4; j++) {
            u64 tv;
            ADD2(tv, av[j], nmu);
            MUL2(tv, tv, rsd);
            FMA2(tv, tv, lsv[j], lbv[j]);
            float y0, y1;
            upk2(y0, y1, tv);
            y0 = fmaxf(y0, 0.f);
            y1 = fmaxf(y1, 0.f);
            if (l < 7) {
                xrow[nn[j]]     = pk2(y0, y0);      // duplicated for next layer
                xrow[nn[j] + 1] = pk2(y1, y1);
            }
            av[j] = pk2(y0, y1);
        }
        a0 = av[0]; a1 = av[1]; a2 = av[2]; a3 = av[3];
        if (l < 7) __syncwarp();
    }

    // ---- rgb head + sigmoid ----
    {
        float y[8];
        upk2(y[0], y[1], a0);
        upk2(y[2], y[3], a1);
        upk2(y[4], y[5], a2);
        upk2(y[6], y[7], a3);
        const int nn0[2] = { nlo, nlo + 32 };
        float r0 = 0.f, r1 = 0.f, r2 = 0.f;
        #pragma unroll
        for (int gq = 0; gq < 2; gq++) {
            #pragma unroll
            for (int j = 0; j < 4; j++) {
                float v = y[gq * 4 + j];
                int n = nn0[gq] + j;
                r0 = fmaf(v, __ldg(rgb_W + n * 3 + 0), r0);
                r1 = fmaf(v, __ldg(rgb_W + n * 3 + 1), r1);
                r2 = fmaf(v, __ldg(rgb_W + n * 3 + 2), r2);
            }
        }
        #pragma unroll
        for (int mm = 1; mm < 8; mm <<= 1) {
            r0 += __shfl_xor_sync(0xffffffffu, r0, mm, 32);
            r1 += __shfl_xor_sync(0xffffffffu, r1, mm, 32);
            r2 += __shfl_xor_sync(0xffffffffu, r2, mm, 32);
        }
        if (ng == 0) {
            out[gpt * 3 + 0] = 1.f / (1.f + expf(-(r0 + __ldg(rgb_b + 0))));
            out[gpt * 3 + 1] = 1.f / (1.f + expf(-(r1 + __ldg(rgb_b + 1))));
            out[gpt * 3 + 2] = 1.f / (1.f + expf(-(r2 + __ldg(rgb_b + 2))));
        }
    }
}

// ---------------------------------------------------------------------------
extern "C" void kernel_launch(void* const* d_in, const int* in_sizes, int n_in,
                              void* d_out, int out_size)
{
    const float* rays    = (const float*)d_in[0];
    const float* lat     = (const float*)d_in[1];
    const float* temb    = (const float*)d_in[2];
    const float* h_W0    = (const float*)d_in[3];
    const float* h_b0    = (const float*)d_in[4];
    const float* h_ln_s0 = (const float*)d_in[5];
    const float* h_ln_b0 = (const float*)d_in[6];
    const float* w_W0    = (const float*)d_in[7];
    const float* w_b0    = (const float*)d_in[8];
    const float* bb_W0   = (const float*)d_in[9];
    const float* bb_b0   = (const float*)d_in[10];
    const float* ln_s0   = (const float*)d_in[11];
    const float* ln_b0   = (const float*)d_in[12];
    const float* h_W     = (const float*)d_in[13];
    const float* h_b     = (const float*)d_in[14];
    const float* h_ln_s  = (const float*)d_in[15];
    const float* h_ln_b  = (const float*)d_in[16];
    const float* w_W     = (const float*)d_in[17];
    const float* w_b     = (const float*)d_in[18];
    const float* bb_W    = (const float*)d_in[19];
    const float* bb_b    = (const float*)d_in[20];
    const float* ln_s    = (const float*)d_in[21];
    const float* ln_b    = (const float*)d_in[22];
    const float* rgb_W   = (const float*)d_in[23];
    const float* rgb_b   = (const float*)d_in[24];
    float* out = (float*)d_out;

    // weights 147456 B + dup-x 64*133*8 = 68096 B  => 215552 B
    const int SMEM = 9216 * 16 + 64 * XSTRIDE * 8;
    cudaFuncSetAttribute(decode_kernel,
                         cudaFuncAttributeMaxDynamicSharedMemorySize, SMEM);

    hyper_kernel<<<256, 512>>>(lat, temb, h_W0, h_b0, h_ln_s0, h_ln_b0,
                               w_W0, w_b0, bb_W0, bb_b0,
                               h_W, h_b, h_ln_s, h_ln_b,
                               w_W, w_b, bb_W, bb_b);
    decode_kernel<<<128, 512, SMEM>>>(rays, ln_s0, ln_b0, ln_s, ln_b,
                                      rgb_W, rgb_b, out);
}

// round 12
// speedup vs baseline: 1.4309x; 1.4309x over previous
#include <cuda_runtime.h>
#include <math.h>

// ---------------------------------------------------------------------------
// HyperNetworkDecoder: K=2, P=4096, 8 layers of width 64.
// hyper_kernel: generate per-(k,layer) weights once, stored m-pair-packed:
//   u64(W[2m2][n], W[2m2+1][n]), rows of 32 ulonglong2 with thread-chunks
//   i-major so warp LDS.128 reads are 128B-contiguous (conflict-free).
// decode_kernel: f32x2 mainloop with m-parity packed accumulators: the x
// operand is a plain LDS.64 (x[2m2],x[2m2+1]) and the w operand comes
// straight from smem — zero packing MOVs. 16 FMA2 : 6 LDS per m2-step.
// R12 fix vs R11: point p0+1's accumulators now get the bias too.
// ---------------------------------------------------------------------------

#define KB 2
typedef unsigned long long u64;

__device__ __align__(16) float g_W0[KB * 64 * 128];      // [k][m2=64][packed row 128f]
__device__ __align__(16) float g_Wl[KB * 7 * 32 * 128];  // [k][l-1][m2=32][row 128f]
__device__ __align__(16) float g_b [KB * 8 * 64];        // biases [k][l][n]

// packed float index within a 128-float row for (n, parity)
__device__ __forceinline__ int wslot(int n, int par)
{
    int c = n >> 1;                       // logical ull2 chunk 0..31
    int s = (c & 3) * 8 + (c >> 2);       // i-major storage position
    return s * 4 + (n & 1) * 2 + par;
}

// ---------------------------------------------------------------------------
// Kernel 1: hypernetwork. grid = (k,l) x 16 output-splits = 256 blocks,
// 512 threads: 2 j-groups of 256 handle half the 64-deep reduction each.
// ---------------------------------------------------------------------------
__global__ void __launch_bounds__(512) hyper_kernel(
    const float* __restrict__ latent_tokens,
    const float* __restrict__ token_embeddings,
    const float* __restrict__ h_W0,  const float* __restrict__ h_b0,
    const float* __restrict__ h_ln_s0, const float* __restrict__ h_ln_b0,
    const float* __restrict__ w_W0,  const float* __restrict__ w_b0,
    const float* __restrict__ bb_W0, const float* __restrict__ bb_b0,
    const float* __restrict__ h_W,   const float* __restrict__ h_b,
    const float* __restrict__ h_ln_s, const float* __restrict__ h_ln_b,
    const float* __restrict__ w_W,   const float* __restrict__ w_b,
    const float* __restrict__ bb_W,  const float* __restrict__ bb_b)
{
    __shared__ float chunk[128];
    __shared__ float part[4][64];
    __shared__ float pre[64];
    __shared__ float hbuf[64];
    __shared__ float wpart[1024];

    const int tid = threadIdx.x;
    const int bx  = blockIdx.x;
    const int sp  = bx & 15;
    const int kl  = bx >> 4;
    const int k   = kl >> 3;
    const int l   = kl & 7;

    if (tid < 128)
        chunk[tid] = (tid < 64) ? latent_tokens[(k * 8 + l) * 64 + tid]
                                : token_embeddings[l * 64 + (tid - 64)];
    __syncthreads();

    const float* hWp = (l == 0) ? h_W0 : (h_W + (l - 1) * 128 * 64);
    if (tid < 256) {
        const int q = tid >> 6, j = tid & 63;
        float acc = 0.f;
        #pragma unroll
        for (int i = 0; i < 32; i++) {
            int ii = q * 32 + i;
            acc = fmaf(chunk[ii], __ldg(hWp + ii * 64 + j), acc);
        }
        part[q][j] = acc;
    }
    __syncthreads();
    if (tid < 64) {
        float hb = (l == 0) ? __ldg(h_b0 + tid) : __ldg(h_b + (l - 1) * 64 + tid);
        pre[tid] = part[0][tid] + part[1][tid] + part[2][tid] + part[3][tid] + hb;
    }
    __syncthreads();
    if (tid < 64) {
        float s1 = 0.f, s2 = 0.f;
        #pragma unroll 8
        for (int i = 0; i < 64; i++) { float v = pre[i]; s1 += v; s2 += v * v; }
        float mu   = s1 * (1.f / 64.f);
        float var  = s2 * (1.f / 64.f) - mu * mu;
        float rstd = rsqrtf(var + 1e-6f);
        float ls = (l == 0) ? __ldg(h_ln_s0 + tid) : __ldg(h_ln_s + (l - 1) * 64 + tid);
        float lb = (l == 0) ? __ldg(h_ln_b0 + tid) : __ldg(h_ln_b + (l - 1) * 64 + tid);
        float h  = fmaf((pre[tid] - mu) * rstd, ls, lb);
        hbuf[tid] = fmaxf(h, 0.f);
    }
    __syncthreads();

    const int OUT  = (l == 0) ? 8064 : 4096;
    const int CH   = OUT >> 4;
    const int o0   = sp * CH, oend = o0 + CH;
    const float* wWp = (l == 0) ? w_W0 : (w_W + (l - 1) * 64 * 4096);
    const float* wbp = (l == 0) ? w_b0 : (w_b + (l - 1) * 4096);

    const int g  = tid >> 8;
    const int tt = tid & 255;

    float acc[2];
    #pragma unroll
    for (int i = 0; i < 2; i++) {
        int o = o0 + tt + i * 256;
        acc[i] = (o < oend && g == 0) ? __ldg(wbp + o) : 0.f;
    }
    const int j0 = g * 32;
    #pragma unroll 8
    for (int jj = 0; jj < 32; jj++) {
        float hj = hbuf[j0 + jj];
        const float* row = wWp + (j0 + jj) * OUT;
        #pragma unroll
        for (int i = 0; i < 2; i++) {
            int o = o0 + tt + i * 256;
            if (o < oend) acc[i] = fmaf(hj, __ldg(row + o), acc[i]);
        }
    }
    wpart[g * 512 + tt]       = acc[0];
    wpart[g * 512 + 256 + tt] = acc[1];
    __syncthreads();

    if (g == 0) {
        #pragma unroll
        for (int i = 0; i < 2; i++) {
            int o = o0 + tt + i * 256;
            if (o < oend) {
                float v = acc[i] + wpart[512 + i * 256 + tt];
                if (l == 0) {
                    int n = o / 126, m = o - n * 126;          // in = 126
                    g_W0[k * 8192 + (m >> 1) * 128 + wslot(n, m & 1)] = v;
                } else {
                    int n = o >> 6, m = o & 63;                // in = 64
                    g_Wl[k * 28672 + (l - 1) * 4096 + (m >> 1) * 128 + wslot(n, m & 1)] = v;
                }
            }
        }
    }

    if (sp == 0) {
        if (l == 0 && tid < 128)          // zero-pad m = 126,127 (row m2 = 63)
            g_W0[k * 8192 + 8064 + tid] = 0.f;
        if (tid < 64) {
            const float* bWp = (l == 0) ? bb_W0 : (bb_W + (l - 1) * 64 * 64);
            float accb = (l == 0) ? __ldg(bb_b0 + tid) : __ldg(bb_b + (l - 1) * 64 + tid);
            #pragma unroll 8
            for (int j = 0; j < 64; j++)
                accb = fmaf(hbuf[j], __ldg(bWp + j * 64 + tid), accb);
            g_b[(k * 8 + l) * 64 + tid] = accb;
        }
    }
}

// ---------------------------------------------------------------------------
// Packed fp32 (f32x2) primitives.
// ---------------------------------------------------------------------------
#define FMA2(D, A, B, C) asm("fma.rn.f32x2 %0, %1, %2, %3;" : "=l"(D) : "l"(A), "l"(B), "l"(C))
#define ADD2(D, A, B)    asm("add.rn.f32x2 %0, %1, %2;"     : "=l"(D) : "l"(A), "l"(B))

__device__ __forceinline__ u64 pk2(float lo, float hi)
{ u64 d; asm("mov.b64 %0, {%1,%2};" : "=l"(d) : "f"(lo), "f"(hi)); return d; }
__device__ __forceinline__ void upk2(float& lo, float& hi, u64 s)
{ asm("mov.b64 {%0,%1}, %2;" : "=f"(lo), "=f"(hi) : "l"(s)); }

// ---------------------------------------------------------------------------
// Float-only accurate sin: 2-term Cody-Waite reduction by pi, then sinf.
// ---------------------------------------------------------------------------
__device__ __forceinline__ float acc_sin(float x)
{
    float q = rintf(x * 0.318309886183790672f);
    float r = fmaf(-q, 3.14159274101257324f, x);
    r = fmaf(-q, -8.74227800037e-8f, r);
    float s = sinf(r);
    return (((int)q) & 1) ? -s : s;
}

// ---------------------------------------------------------------------------
// Kernel 2: decoder. 128 blocks x 256 threads, 64 points/block (one k).
// Warp wp owns points 8wp..8wp+7. Lane (pq = lane>>3, ng = lane&7):
// thread computes outputs n0=8ng..n0+7 for points p0 = 8wp+2pq and p0+1.
// 16 u64 accs = (even-m partial, odd-m partial) per output.
// ---------------------------------------------------------------------------
#define XSTRIDE 132

__global__ void __launch_bounds__(256, 1) decode_kernel(
    const float* __restrict__ rays,
    const float* __restrict__ ln_s0, const float* __restrict__ ln_b0,
    const float* __restrict__ ln_s,  const float* __restrict__ ln_b,
    const float* __restrict__ rgb_W, const float* __restrict__ rgb_b,
    float* __restrict__ out)
{
    extern __shared__ float smem[];
    float4* sW = (float4*)smem;            // 9216 float4: W0(2048) + Wl(7168)
    float*  xs = (float*)(sW + 9216);      // 64 pts * 132 floats

    const int tid  = threadIdx.x;
    const int wp   = tid >> 5;
    const int lane = tid & 31;
    const int pq   = lane >> 3;            // point-pair 0..3
    const int ng   = lane & 7;             // n-group 0..7
    const int n0   = 8 * ng;
    const int k    = blockIdx.x >> 6;
    const int p0   = 8 * wp + 2 * pq;
    const int gpt0 = blockIdx.x * 64 + p0;

    // ---- weight load (coalesced, 36 float4/thread; layout preserved) ----
    {
        const float4* s0 = (const float4*)g_W0 + k * 2048;
        const float4* s1 = (const float4*)g_Wl + k * 7168;
        #pragma unroll
        for (int i = 0; i < 8; i++)  sW[tid + i * 256] = __ldg(s0 + tid + i * 256);
        #pragma unroll
        for (int i = 0; i < 28; i++) sW[2048 + tid + i * 256] = __ldg(s1 + tid + i * 256);
    }

    // ---- positional encoding: 4 lanes per point (pp = lane>>2, s = lane&3) ----
    {
        const int pp = lane >> 2;          // point 0..7 within warp
        const int s  = lane & 3;
        float* xrow  = xs + (8 * wp + pp) * XSTRIDE;
        const float* r = rays + (blockIdx.x * 64 + 8 * wp + pp) * 6;
        float ox = __ldg(r + 0), oy = __ldg(r + 1), oz = __ldg(r + 2);
        float dx = __ldg(r + 3), dy = __ldg(r + 4), dz = __ldg(r + 5);
        float pl[6];
        pl[0] = dx; pl[1] = dy; pl[2] = dz;
        pl[3] = oy * dz - oz * dy;
        pl[4] = oz * dx - ox * dz;
        pl[5] = ox * dy - oy * dx;
        if (s == 3) {
            #pragma unroll
            for (int cm = 0; cm < 6; cm++) xrow[cm] = pl[cm];
            xrow[126] = 0.f;
            xrow[127] = 0.f;
        }
        const float PIH = 1.57079632679489662f;
        for (int f = s; f < 10; f += 4) {
            float fr = (float)(1 << f);
            #pragma unroll
            for (int cm = 0; cm < 6; cm++) {
                float a = pl[cm] * fr;
                xrow[6 + f * 6 + cm]  = acc_sin(a);
                xrow[66 + f * 6 + cm] = acc_sin(a + PIH);
            }
        }
    }
    __syncthreads();   // the ONLY block barrier

    const float* bb  = g_b + k * 512;
    float* xr0 = xs + p0 * XSTRIDE;
    float* xr1 = xr0 + XSTRIDE;

    u64 a[16];                 // [point(2)][j(8)] — (even, odd) m-partials
    float y0[8], y1[8];

    #pragma unroll 1
    for (int l = 0; l < 8; l++) {
        const ulonglong2* Wt = (l == 0)
            ? (const ulonglong2*)sW
            : (const ulonglong2*)(sW + 2048 + (l - 1) * 1024);
        const int M2 = (l == 0) ? 64 : 32;

        {   // bias in the even lane only (y = lo + hi at the end)
            // R12 FIX: BOTH points get the bias (R11 left a[8..15] at zero).
            float4 ba = __ldg((const float4*)(bb + l * 64 + n0));
            float4 bc = __ldg((const float4*)(bb + l * 64 + n0 + 4));
            a[0] = pk2(ba.x, 0.f); a[1] = pk2(ba.y, 0.f);
            a[2] = pk2(ba.z, 0.f); a[3] = pk2(ba.w, 0.f);
            a[4] = pk2(bc.x, 0.f); a[5] = pk2(bc.y, 0.f);
            a[6] = pk2(bc.z, 0.f); a[7] = pk2(bc.w, 0.f);
            #pragma unroll
            for (int j = 0; j < 8; j++) a[8 + j] = a[j];
        }

        #pragma unroll 8
        for (int m2 = 0; m2 < M2; m2++) {
            const ulonglong2* row = Wt + m2 * 32 + ng;
            ulonglong2 w0 = row[0];        // n0+0, n0+1
            ulonglong2 w1 = row[8];        // n0+2, n0+3
            ulonglong2 w2 = row[16];       // n0+4, n0+5
            ulonglong2 w3 = row[24];       // n0+6, n0+7
            u64 x0 = *(const u64*)(xr0 + 2 * m2);   // (x[2m2], x[2m2+1])
            u64 x1 = *(const u64*)(xr1 + 2 * m2);
            FMA2(a[0],  x0, w0.x, a[0]);  FMA2(a[1],  x0, w0.y, a[1]);
            FMA2(a[2],  x0, w1.x, a[2]);  FMA2(a[3],  x0, w1.y, a[3]);
            FMA2(a[4],  x0, w2.x, a[4]);  FMA2(a[5],  x0, w2.y, a[5]);
            FMA2(a[6],  x0, w3.x, a[6]);  FMA2(a[7],  x0, w3.y, a[7]);
            FMA2(a[8],  x1, w0.x, a[8]);  FMA2(a[9],  x1, w0.y, a[9]);
            FMA2(a[10], x1, w1.x, a[10]); FMA2(a[11], x1, w1.y, a[11]);
            FMA2(a[12], x1, w2.x, a[12]); FMA2(a[13], x1, w2.y, a[13]);
            FMA2(a[14], x1, w3.x, a[14]); FMA2(a[15], x1, w3.y, a[15]);
        }

        // ---- collapse parities, LayerNorm + relu ----
        float s1a = 0.f, s2a = 0.f, s1b = 0.f, s2b = 0.f;
        #pragma unroll
        for (int j = 0; j < 8; j++) {
            float lo, hi;
            upk2(lo, hi, a[j]);
            float y = lo + hi;
            y0[j] = y; s1a += y; s2a = fmaf(y, y, s2a);
            upk2(lo, hi, a[8 + j]);
            y = lo + hi;
            y1[j] = y; s1b += y; s2b = fmaf(y, y, s2b);
        }
        u64 S1 = pk2(s1a, s1b);
        u64 S2 = pk2(s2a, s2b);
        #pragma unroll
        for (int mm = 1; mm < 8; mm <<= 1) {
            u64 o1 = __shfl_xor_sync(0xffffffffu, S1, mm, 32);
            u64 o2 = __shfl_xor_sync(0xffffffffu, S2, mm, 32);
            ADD2(S1, S1, o1);
            ADD2(S2, S2, o2);
        }
        upk2(s1a, s1b, S1);
        upk2(s2a, s2b, S2);
        float mu0 = s1a * (1.f / 64.f), mu1 = s1b * (1.f / 64.f);
        float rs0 = rsqrtf(s2a * (1.f / 64.f) - mu0 * mu0 + 1e-6f);
        float rs1 = rsqrtf(s2b * (1.f / 64.f) - mu1 * mu1 + 1e-6f);

        const float* lns = (l == 0) ? ln_s0 : (ln_s + (l - 1) * 64);
        const float* lnb = (l == 0) ? ln_b0 : (ln_b + (l - 1) * 64);
        float4 lsa = __ldg((const float4*)(lns + n0));
        float4 lsb = __ldg((const float4*)(lns + n0 + 4));
        float4 lba = __ldg((const float4*)(lnb + n0));
        float4 lbb = __ldg((const float4*)(lnb + n0 + 4));
        float lsv[8] = { lsa.x, lsa.y, lsa.z, lsa.w, lsb.x, lsb.y, lsb.z, lsb.w };
        float lbv[8] = { lba.x, lba.y, lba.z, lba.w, lbb.x, lbb.y, lbb.z, lbb.w };

        #pragma unroll
        for (int j = 0; j < 8; j++) {
            y0[j] = fmaxf(fmaf((y0[j] - mu0) * rs0, lsv[j], lbv[j]), 0.f);
            y1[j] = fmaxf(fmaf((y1[j] - mu1) * rs1, lsv[j], lbv[j]), 0.f);
        }

        if (l < 7) {
            *(float4*)(xr0 + n0)     = make_float4(y0[0], y0[1], y0[2], y0[3]);
            *(float4*)(xr0 + n0 + 4) = make_float4(y0[4], y0[5], y0[6], y0[7]);
            *(float4*)(xr1 + n0)     = make_float4(y1[0], y1[1], y1[2], y1[3]);
            *(float4*)(xr1 + n0 + 4) = make_float4(y1[4], y1[5], y1[6], y1[7]);
            __syncwarp();
        }
    }

    // ---- rgb head + sigmoid ----
    {
        float r0a = 0.f, r1a = 0.f, r2a = 0.f;
        float r0b = 0.f, r1b = 0.f, r2b = 0.f;
        #pragma unroll
        for (int j = 0; j < 8; j++) {
            int n = n0 + j;
            float w0 = __ldg(rgb_W + n * 3 + 0);
            float w1 = __ldg(rgb_W + n * 3 + 1);
            float w2 = __ldg(rgb_W + n * 3 + 2);
            r0a = fmaf(y0[j], w0, r0a);  r0b = fmaf(y1[j], w0, r0b);
            r1a = fmaf(y0[j], w1, r1a);  r1b = fmaf(y1[j], w1, r1b);
            r2a = fmaf(y0[j], w2, r2a);  r2b = fmaf(y1[j], w2, r2b);
        }
        u64 R0 = pk2(r0a, r0b), R1 = pk2(r1a, r1b), R2 = pk2(r2a, r2b);
        #pragma unroll
        for (int mm = 1; mm < 8; mm <<= 1) {
            u64 t0 = __shfl_xor_sync(0xffffffffu, R0, mm, 32);
            u64 t1 = __shfl_xor_sync(0xffffffffu, R1, mm, 32);
            u64 t2 = __shfl_xor_sync(0xffffffffu, R2, mm, 32);
            ADD2(R0, R0, t0);
            ADD2(R1, R1, t1);
            ADD2(R2, R2, t2);
        }
        if (ng == 0) {
            float b0 = __ldg(rgb_b + 0), b1 = __ldg(rgb_b + 1), b2 = __ldg(rgb_b + 2);
            float v0a, v0b, v1a, v1b, v2a, v2b;
            upk2(v0a, v0b, R0);
            upk2(v1a, v1b, R1);
            upk2(v2a, v2b, R2);
            out[gpt0 * 3 + 0]       = 1.f / (1.f + expf(-(v0a + b0)));
            out[gpt0 * 3 + 1]       = 1.f / (1.f + expf(-(v1a + b1)));
            out[gpt0 * 3 + 2]       = 1.f / (1.f + expf(-(v2a + b2)));
            out[(gpt0 + 1) * 3 + 0] = 1.f / (1.f + expf(-(v0b + b0)));
            out[(gpt0 + 1) * 3 + 1] = 1.f / (1.f + expf(-(v1b + b1)));
            out[(gpt0 + 1) * 3 + 2] = 1.f / (1.f + expf(-(v2b + b2)));
        }
    }
}

// ---------------------------------------------------------------------------
extern "C" void kernel_launch(void* const* d_in, const int* in_sizes, int n_in,
                              void* d_out, int out_size)
{
    const float* rays    = (const float*)d_in[0];
    const float* lat     = (const float*)d_in[1];
    const float* temb    = (const float*)d_in[2];
    const float* h_W0    = (const float*)d_in[3];
    const float* h_b0    = (const float*)d_in[4];
    const float* h_ln_s0 = (const float*)d_in[5];
    const float* h_ln_b0 = (const float*)d_in[6];
    const float* w_W0    = (const float*)d_in[7];
    const float* w_b0    = (const float*)d_in[8];
    const float* bb_W0   = (const float*)d_in[9];
    const float* bb_b0   = (const float*)d_in[10];
    const float* ln_s0   = (const float*)d_in[11];
    const float* ln_b0   = (const float*)d_in[12];
    const float* h_W     = (const float*)d_in[13];
    const float* h_b     = (const float*)d_in[14];
    const float* h_ln_s  = (const float*)d_in[15];
    const float* h_ln_b  = (const float*)d_in[16];
    const float* w_W     = (const float*)d_in[17];
    const float* w_b     = (const float*)d_in[18];
    const float* bb_W    = (const float*)d_in[19];
    const float* bb_b    = (const float*)d_in[20];
    const float* ln_s    = (const float*)d_in[21];
    const float* ln_b    = (const float*)d_in[22];
    const float* rgb_W   = (const float*)d_in[23];
    const float* rgb_b   = (const float*)d_in[24];
    float* out = (float*)d_out;

    // weights 147456 B + x 64*132*4 = 33792 B => 181248 B
    const int SMEM = 9216 * 16 + 64 * XSTRIDE * 4;
    cudaFuncSetAttribute(decode_kernel,
                         cudaFuncAttributeMaxDynamicSharedMemorySize, SMEM);

    hyper_kernel<<<256, 512>>>(lat, temb, h_W0, h_b0, h_ln_s0, h_ln_b0,
                               w_W0, w_b0, bb_W0, bb_b0,
                               h_W, h_b, h_ln_s, h_ln_b,
                               w_W, w_b, bb_W, bb_b);
    decode_kernel<<<128, 256, SMEM>>>(rays, ln_s0, ln_b0, ln_s, ln_b,
                                      rgb_W, rgb_b, out);
}

// round 13
// speedup vs baseline: 2.2975x; 1.6057x over previous
#include <cuda_runtime.h>
#include <math.h>

// ---------------------------------------------------------------------------
// HyperNetworkDecoder: K=2, P=4096, 8 layers of width 64.
// hyper_kernel: generate per-(k,layer) weights once, stored directly as
// tf32 B-fragments for mma.sync.m16n8k8 (b0=B[k%4][n/..], b1=B[k%4+4][..]).
// decode_kernel: tensor-core decoder. Warp owns 16 points x all 64 outputs;
// A fragments (x) live in warp-private smem in fragment layout; per layer:
// 8(16) ktiles x 8 ntiles mma, shuffle LayerNorm in fp32, epilogue re-writes
// next layer's A fragments. No block barrier after the prologue.
// ---------------------------------------------------------------------------

#define KB 2
typedef unsigned int u32;

__device__ __align__(16) u32 g_W0u[KB * 8192];          // l0 W  B-frag tf32 [k][fi*64+lane*2+slot]
__device__ __align__(16) u32 g_Wlu[KB * 7 * 4096];      // l1..7 W B-frag tf32
__device__ __align__(16) float g_b [KB * 8 * 64];       // biases [k][l][n]

__device__ __forceinline__ u32 tf32c(float f)
{ u32 u; asm("cvt.rna.tf32.f32 %0, %1;" : "=r"(u) : "f"(f)); return u; }

// ---------------------------------------------------------------------------
// Kernel 1: hypernetwork. grid = (k,l) x 16 output-splits = 256 blocks,
// 512 threads: 2 j-groups of 256 handle half the 64-deep reduction each.
// ---------------------------------------------------------------------------
__global__ void __launch_bounds__(512) hyper_kernel(
    const float* __restrict__ latent_tokens,
    const float* __restrict__ token_embeddings,
    const float* __restrict__ h_W0,  const float* __restrict__ h_b0,
    const float* __restrict__ h_ln_s0, const float* __restrict__ h_ln_b0,
    const float* __restrict__ w_W0,  const float* __restrict__ w_b0,
    const float* __restrict__ bb_W0, const float* __restrict__ bb_b0,
    const float* __restrict__ h_W,   const float* __restrict__ h_b,
    const float* __restrict__ h_ln_s, const float* __restrict__ h_ln_b,
    const float* __restrict__ w_W,   const float* __restrict__ w_b,
    const float* __restrict__ bb_W,  const float* __restrict__ bb_b)
{
    __shared__ float chunk[128];
    __shared__ float part[4][64];
    __shared__ float pre[64];
    __shared__ float hbuf[64];
    __shared__ float wpart[1024];

    const int tid = threadIdx.x;
    const int bx  = blockIdx.x;
    const int sp  = bx & 15;
    const int kl  = bx >> 4;
    const int k   = kl >> 3;
    const int l   = kl & 7;

    if (tid < 128)
        chunk[tid] = (tid < 64) ? latent_tokens[(k * 8 + l) * 64 + tid]
                                : token_embeddings[l * 64 + (tid - 64)];
    __syncthreads();

    const float* hWp = (l == 0) ? h_W0 : (h_W + (l - 1) * 128 * 64);
    if (tid < 256) {
        const int q = tid >> 6, j = tid & 63;
        float acc = 0.f;
        #pragma unroll
        for (int i = 0; i < 32; i++) {
            int ii = q * 32 + i;
            acc = fmaf(chunk[ii], __ldg(hWp + ii * 64 + j), acc);
        }
        part[q][j] = acc;
    }
    __syncthreads();
    if (tid < 64) {
        float hb = (l == 0) ? __ldg(h_b0 + tid) : __ldg(h_b + (l - 1) * 64 + tid);
        pre[tid] = part[0][tid] + part[1][tid] + part[2][tid] + part[3][tid] + hb;
    }
    __syncthreads();
    if (tid < 64) {
        float s1 = 0.f, s2 = 0.f;
        #pragma unroll 8
        for (int i = 0; i < 64; i++) { float v = pre[i]; s1 += v; s2 += v * v; }
        float mu   = s1 * (1.f / 64.f);
        float var  = s2 * (1.f / 64.f) - mu * mu;
        float rstd = rsqrtf(var + 1e-6f);
        float ls = (l == 0) ? __ldg(h_ln_s0 + tid) : __ldg(h_ln_s + (l - 1) * 64 + tid);
        float lb = (l == 0) ? __ldg(h_ln_b0 + tid) : __ldg(h_ln_b + (l - 1) * 64 + tid);
        float h  = fmaf((pre[tid] - mu) * rstd, ls, lb);
        hbuf[tid] = fmaxf(h, 0.f);
    }
    __syncthreads();

    const int OUT  = (l == 0) ? 8064 : 4096;
    const int CH   = OUT >> 4;
    const int o0   = sp * CH, oend = o0 + CH;
    const float* wWp = (l == 0) ? w_W0 : (w_W + (l - 1) * 64 * 4096);
    const float* wbp = (l == 0) ? w_b0 : (w_b + (l - 1) * 4096);

    const int g  = tid >> 8;
    const int tt = tid & 255;

    float acc[2];
    #pragma unroll
    for (int i = 0; i < 2; i++) {
        int o = o0 + tt + i * 256;
        acc[i] = (o < oend && g == 0) ? __ldg(wbp + o) : 0.f;
    }
    const int j0 = g * 32;
    #pragma unroll 8
    for (int jj = 0; jj < 32; jj++) {
        float hj = hbuf[j0 + jj];
        const float* row = wWp + (j0 + jj) * OUT;
        #pragma unroll
        for (int i = 0; i < 2; i++) {
            int o = o0 + tt + i * 256;
            if (o < oend) acc[i] = fmaf(hj, __ldg(row + o), acc[i]);
        }
    }
    wpart[g * 512 + tt]       = acc[0];
    wpart[g * 512 + 256 + tt] = acc[1];
    __syncthreads();

    if (g == 0) {
        #pragma unroll
        for (int i = 0; i < 2; i++) {
            int o = o0 + tt + i * 256;
            if (o < oend) {
                float v = acc[i] + wpart[512 + i * 256 + tt];
                int n, m;
                if (l == 0) { n = o / 126; m = o - n * 126; }
                else        { n = o >> 6;  m = o & 63; }
                // B-fragment layout: B[k=m][n], b0: k=lane%4, n=lane/4; b1: k=lane%4+4
                int kt = m >> 3, kk = m & 7;
                int nt = n >> 3, nn = n & 7;
                int lane = nn * 4 + (kk & 3);
                int slot = kk >> 2;
                int idx  = (kt * 8 + nt) * 64 + lane * 2 + slot;
                if (l == 0) g_W0u[k * 8192 + idx] = tf32c(v);
                else        g_Wlu[k * 28672 + (l - 1) * 4096 + idx] = tf32c(v);
            }
        }
    }

    if (sp == 0) {
        if (l == 0 && tid < 128) {        // zero-pad m = 126,127 for all n
            int n = tid & 63, m = 126 + (tid >> 6);
            int kt = m >> 3, kk = m & 7;
            int nt = n >> 3, nn = n & 7;
            int idx = (kt * 8 + nt) * 64 + (nn * 4 + (kk & 3)) * 2 + (kk >> 2);
            g_W0u[k * 8192 + idx] = 0u;
        }
        if (tid < 64) {
            const float* bWp = (l == 0) ? bb_W0 : (bb_W + (l - 1) * 64 * 64);
            float accb = (l == 0) ? __ldg(bb_b0 + tid) : __ldg(bb_b + (l - 1) * 64 + tid);
            #pragma unroll 8
            for (int j = 0; j < 64; j++)
                accb = fmaf(hbuf[j], __ldg(bWp + j * 64 + tid), accb);
            g_b[(k * 8 + l) * 64 + tid] = accb;
        }
    }
}

// ---------------------------------------------------------------------------
// Float-only accurate sin: 2-term Cody-Waite reduction by pi, then sinf.
// ---------------------------------------------------------------------------
__device__ __forceinline__ float acc_sin(float x)
{
    float q = rintf(x * 0.318309886183790672f);
    float r = fmaf(-q, 3.14159274101257324f, x);
    r = fmaf(-q, -8.74227800037e-8f, r);
    float s = sinf(r);
    return (((int)q) & 1) ? -s : s;
}

#define MMA_TF32(C, AV, BV) \
    asm volatile("mma.sync.aligned.m16n8k8.row.col.f32.tf32.tf32.f32 " \
        "{%0,%1,%2,%3}, {%4,%5,%6,%7}, {%8,%9}, {%0,%1,%2,%3};" \
        : "+f"((C)[0]), "+f"((C)[1]), "+f"((C)[2]), "+f"((C)[3]) \
        : "r"((AV).x), "r"((AV).y), "r"((AV).z), "r"((AV).w), \
          "r"((BV).x), "r"((BV).y))

// ---------------------------------------------------------------------------
// Kernel 2: tensor-core decoder. 128 blocks x 256 threads, 64 pts/block.
// Warps 0..3 each own 16 points (A-tile warp-private); warps 4..7 help the
// prologue then exit. Per layer: KT ktiles x 8 ntiles of m16n8k8 tf32 mma,
// fp32 shuffle-LN, epilogue stores next A fragments. __syncwarp only.
// ---------------------------------------------------------------------------
__global__ void __launch_bounds__(256, 1) decode_kernel(
    const float* __restrict__ rays,
    const float* __restrict__ ln_s0, const float* __restrict__ ln_b0,
    const float* __restrict__ ln_s,  const float* __restrict__ ln_b,
    const float* __restrict__ rgb_W, const float* __restrict__ rgb_b,
    float* __restrict__ out)
{
    extern __shared__ u32 smem_u[];
    u32*   sW    = smem_u;                        // 36864 u32 (W0 8192 + Wl 28672)
    u32*   sA    = smem_u + 36864;                // 8192 u32 (4 warps x 2048)
    float* sBias = (float*)(smem_u + 45056);      // 512
    float* sLN   = (float*)(smem_u + 45568);      // 1024 (8 layers x [s64|b64])

    const int tid  = threadIdx.x;
    const int wid  = tid >> 5;
    const int lane = tid & 31;
    const int k    = blockIdx.x >> 6;
    const int bx   = blockIdx.x;

    // ---- stage weights (frag layout preserved) ----
    {
        const uint4* s0 = (const uint4*)(g_W0u + k * 8192);     // 2048 uint4
        const uint4* s1 = (const uint4*)(g_Wlu + k * 28672);    // 7168 uint4
        #pragma unroll
        for (int i = 0; i < 8; i++)  ((uint4*)sW)[tid + i * 256] = __ldg(s0 + tid + i * 256);
        #pragma unroll
        for (int i = 0; i < 28; i++) ((uint4*)(sW + 8192))[tid + i * 256] = __ldg(s1 + tid + i * 256);
    }
    // ---- stage biases + LN params ----
    sBias[tid]       = __ldg(g_b + k * 512 + tid);
    sBias[tid + 256] = __ldg(g_b + k * 512 + 256 + tid);
    for (int i = tid; i < 1024; i += 256) {
        int l = i >> 7, j = i & 127;
        float v;
        if (l == 0) v = (j < 64) ? __ldg(ln_s0 + j) : __ldg(ln_b0 + j - 64);
        else        v = (j < 64) ? __ldg(ln_s + (l - 1) * 64 + j)
                                 : __ldg(ln_b + (l - 1) * 64 + j - 64);
        sLN[i] = v;
    }

    // ---- positional encoding into A-fragment layout (4 lanes/point) ----
    {
        const int pb = tid >> 2;            // point in block 0..63
        const int s  = tid & 3;
        const int pl = pb & 15;
        u32* Ar = sA + (pb >> 4) * 2048;
        const float* r = rays + (bx * 64 + pb) * 6;
        float ox = __ldg(r + 0), oy = __ldg(r + 1), oz = __ldg(r + 2);
        float dx = __ldg(r + 3), dy = __ldg(r + 4), dz = __ldg(r + 5);
        float pv[6];
        pv[0] = dx; pv[1] = dy; pv[2] = dz;
        pv[3] = oy * dz - oz * dy;
        pv[4] = oz * dx - ox * dz;
        pv[5] = ox * dy - oy * dx;
        auto sta = [&](int m, float v) {
            int kt = m >> 3, c = m & 7;
            int ln = (pl & 7) * 4 + (c & 3);
            int sl = (pl >> 3) + 2 * (c >> 2);
            Ar[kt * 128 + ln * 4 + sl] = tf32c(v);
        };
        if (s == 3) {
            #pragma unroll
            for (int cm = 0; cm < 6; cm++) sta(cm, pv[cm]);
            sta(126, 0.f);
            sta(127, 0.f);
        }
        const float PIH = 1.57079632679489662f;
        for (int f = s; f < 10; f += 4) {
            float fr = (float)(1 << f);
            #pragma unroll
            for (int cm = 0; cm < 6; cm++) {
                float a = pv[cm] * fr;
                sta(6 + f * 6 + cm, acc_sin(a));
                sta(66 + f * 6 + cm, acc_sin(a + PIH));
            }
        }
    }
    __syncthreads();          // the ONLY block barrier
    if (wid >= 4) return;     // helper warps done

    u32* At = sA + wid * 2048;
    const int gid = lane >> 2;    // row group 0..7
    const int tig = lane & 3;     // thread in group

    float C[8][4];

    #pragma unroll 1
    for (int l = 0; l < 8; l++) {
        const u32* Wl = (l == 0) ? sW : (sW + 8192 + (l - 1) * 4096);
        const int KT = (l == 0) ? 16 : 8;

        #pragma unroll
        for (int nt = 0; nt < 8; nt++) {
            int n0 = nt * 8 + 2 * tig;
            float b0v = sBias[l * 64 + n0];
            float b1v = sBias[l * 64 + n0 + 1];
            C[nt][0] = b0v; C[nt][1] = b1v;
            C[nt][2] = b0v; C[nt][3] = b1v;
        }

        #pragma unroll 8
        for (int kt = 0; kt < KT; kt++) {
            uint4 av = *(const uint4*)(At + kt * 128 + lane * 4);
            #pragma unroll
            for (int nt = 0; nt < 8; nt++) {
                uint2 bv = *(const uint2*)(Wl + (kt * 8 + nt) * 64 + lane * 2);
                MMA_TF32(C[nt], av, bv);
            }
        }

        // ---- LayerNorm (fp32, shuffle over the 4-lane row group) ----
        float s1 = 0.f, s2 = 0.f, s1b = 0.f, s2b = 0.f;
        #pragma unroll
        for (int nt = 0; nt < 8; nt++) {
            s1  += C[nt][0] + C[nt][1];
            s2   = fmaf(C[nt][0], C[nt][0], fmaf(C[nt][1], C[nt][1], s2));
            s1b += C[nt][2] + C[nt][3];
            s2b  = fmaf(C[nt][2], C[nt][2], fmaf(C[nt][3], C[nt][3], s2b));
        }
        #pragma unroll
        for (int mm = 1; mm < 4; mm <<= 1) {
            s1  += __shfl_xor_sync(0xffffffffu, s1,  mm, 32);
            s2  += __shfl_xor_sync(0xffffffffu, s2,  mm, 32);
            s1b += __shfl_xor_sync(0xffffffffu, s1b, mm, 32);
            s2b += __shfl_xor_sync(0xffffffffu, s2b, mm, 32);
        }
        float mu0 = s1  * (1.f / 64.f);
        float mu1 = s1b * (1.f / 64.f);
        float rs0 = rsqrtf(s2  * (1.f / 64.f) - mu0 * mu0 + 1e-6f);
        float rs1 = rsqrtf(s2b * (1.f / 64.f) - mu1 * mu1 + 1e-6f);

        #pragma unroll
        for (int nt = 0; nt < 8; nt++) {
            int n0 = nt * 8 + 2 * tig;
            float ls0 = sLN[l * 128 + n0],      ls1 = sLN[l * 128 + n0 + 1];
            float lb0 = sLN[l * 128 + 64 + n0], lb1 = sLN[l * 128 + 64 + n0 + 1];
            float y00 = fmaxf(fmaf((C[nt][0] - mu0) * rs0, ls0, lb0), 0.f);
            float y01 = fmaxf(fmaf((C[nt][1] - mu0) * rs0, ls1, lb1), 0.f);
            float y10 = fmaxf(fmaf((C[nt][2] - mu1) * rs1, ls0, lb0), 0.f);
            float y11 = fmaxf(fmaf((C[nt][3] - mu1) * rs1, ls1, lb1), 0.f);
            C[nt][0] = y00; C[nt][1] = y01;
            C[nt][2] = y10; C[nt][3] = y11;
            if (l < 7) {
                int c0 = n0 & 7;                 // even col
                int b0i = nt * 128 + (gid * 4 + (c0 & 3)) * 4 + 2 * (c0 >> 2);
                At[b0i]     = tf32c(y00);        // row gid
                At[b0i + 1] = tf32c(y10);        // row gid+8
                int c1 = c0 + 1;
                int b1i = nt * 128 + (gid * 4 + (c1 & 3)) * 4 + 2 * (c1 >> 2);
                At[b1i]     = tf32c(y01);
                At[b1i + 1] = tf32c(y11);
            }
        }
        if (l < 7) __syncwarp();
    }

    // ---- rgb head + sigmoid (full fp32) ----
    {
        float r[2][3] = {{0.f, 0.f, 0.f}, {0.f, 0.f, 0.f}};
        #pragma unroll
        for (int nt = 0; nt < 8; nt++) {
            int n0 = nt * 8 + 2 * tig;
            #pragma unroll
            for (int ch = 0; ch < 3; ch++) {
                float w0 = __ldg(rgb_W + n0 * 3 + ch);
                float w1 = __ldg(rgb_W + (n0 + 1) * 3 + ch);
                r[0][ch] = fmaf(C[nt][0], w0, fmaf(C[nt][1], w1, r[0][ch]));
                r[1][ch] = fmaf(C[nt][2], w0, fmaf(C[nt][3], w1, r[1][ch]));
            }
        }
        #pragma unroll
        for (int mm = 1; mm < 4; mm <<= 1) {
            #pragma unroll
            for (int p = 0; p < 2; p++)
                #pragma unroll
                for (int ch = 0; ch < 3; ch++)
                    r[p][ch] += __shfl_xor_sync(0xffffffffu, r[p][ch], mm, 32);
        }
        if (tig == 0) {
            int p0 = bx * 64 + wid * 16 + gid;
            #pragma unroll
            for (int ch = 0; ch < 3; ch++) {
                float b = __ldg(rgb_b + ch);
                out[p0 * 3 + ch]       = 1.f / (1.f + expf(-(r[0][ch] + b)));
                out[(p0 + 8) * 3 + ch] = 1.f / (1.f + expf(-(r[1][ch] + b)));
            }
        }
    }
}

// ---------------------------------------------------------------------------
extern "C" void kernel_launch(void* const* d_in, const int* in_sizes, int n_in,
                              void* d_out, int out_size)
{
    const float* rays    = (const float*)d_in[0];
    const float* lat     = (const float*)d_in[1];
    const float* temb    = (const float*)d_in[2];
    const float* h_W0    = (const float*)d_in[3];
    const float* h_b0    = (const float*)d_in[4];
    const float* h_ln_s0 = (const float*)d_in[5];
    const float* h_ln_b0 = (const float*)d_in[6];
    const float* w_W0    = (const float*)d_in[7];
    const float* w_b0    = (const float*)d_in[8];
    const float* bb_W0   = (const float*)d_in[9];
    const float* bb_b0   = (const float*)d_in[10];
    const float* ln_s0   = (const float*)d_in[11];
    const float* ln_b0   = (const float*)d_in[12];
    const float* h_W     = (const float*)d_in[13];
    const float* h_b     = (const float*)d_in[14];
    const float* h_ln_s  = (const float*)d_in[15];
    const float* h_ln_b  = (const float*)d_in[16];
    const float* w_W     = (const float*)d_in[17];
    const float* w_b     = (const float*)d_in[18];
    const float* bb_W    = (const float*)d_in[19];
    const float* bb_b    = (const float*)d_in[20];
    const float* ln_s    = (const float*)d_in[21];
    const float* ln_b    = (const float*)d_in[22];
    const float* rgb_W   = (const float*)d_in[23];
    const float* rgb_b   = (const float*)d_in[24];
    float* out = (float*)d_out;

    // 36864 (W) + 8192 (A) + 512 (bias) + 1024 (LN) = 46592 u32 = 186368 B
    const int SMEM = 46592 * 4;
    cudaFuncSetAttribute(decode_kernel,
                         cudaFuncAttributeMaxDynamicSharedMemorySize, SMEM);

    hyper_kernel<<<256, 512>>>(lat, temb, h_W0, h_b0, h_ln_s0, h_ln_b0,
                               w_W0, w_b0, bb_W0, bb_b0,
                               h_W, h_b, h_ln_s, h_ln_b,
                               w_W, w_b, bb_W, bb_b);
    decode_kernel<<<128, 256, SMEM>>>(rays, ln_s0, ln_b0, ln_s, ln_b,
                                      rgb_W, rgb_b, out);
}

// round 14
// speedup vs baseline: 2.3278x; 1.0132x over previous
#include <cuda_runtime.h>
#include <math.h>

// ---------------------------------------------------------------------------
// HyperNetworkDecoder: K=2, P=4096, 8 layers of width 64.
// hyper_kernel: generate per-(k,layer) weights once, stored directly as
// tf32 B-fragments for mma.sync.m16n8k8.
// decode_kernel: tensor-core decoder, 4-way n-split. 512 threads = 16 warps:
// warp (t = wid&3, ns = wid>>2) computes n-tiles {2ns,2ns+1} of the 16-point
// A-tile t. LayerNorm via tile-local named barrier (bar.sync t+1, 128) and
// a float4 smem partial exchange. 4 warps/SMSP -> latency hidden.
// ---------------------------------------------------------------------------

#define KB 2
typedef unsigned int u32;

__device__ __align__(16) u32 g_W0u[KB * 8192];          // l0 W  B-frag tf32
__device__ __align__(16) u32 g_Wlu[KB * 7 * 4096];      // l1..7 W B-frag tf32
__device__ __align__(16) float g_b [KB * 8 * 64];       // biases [k][l][n]

__device__ __forceinline__ u32 tf32c(float f)
{ u32 u; asm("cvt.rna.tf32.f32 %0, %1;" : "=r"(u) : "f"(f)); return u; }

// ---------------------------------------------------------------------------
// Kernel 1: hypernetwork. grid = (k,l) x 16 output-splits = 256 blocks,
// 512 threads: 2 j-groups of 256 handle half the 64-deep reduction each.
// ---------------------------------------------------------------------------
__global__ void __launch_bounds__(512) hyper_kernel(
    const float* __restrict__ latent_tokens,
    const float* __restrict__ token_embeddings,
    const float* __restrict__ h_W0,  const float* __restrict__ h_b0,
    const float* __restrict__ h_ln_s0, const float* __restrict__ h_ln_b0,
    const float* __restrict__ w_W0,  const float* __restrict__ w_b0,
    const float* __restrict__ bb_W0, const float* __restrict__ bb_b0,
    const float* __restrict__ h_W,   const float* __restrict__ h_b,
    const float* __restrict__ h_ln_s, const float* __restrict__ h_ln_b,
    const float* __restrict__ w_W,   const float* __restrict__ w_b,
    const float* __restrict__ bb_W,  const float* __restrict__ bb_b)
{
    __shared__ float chunk[128];
    __shared__ float part[4][64];
    __shared__ float pre[64];
    __shared__ float hbuf[64];
    __shared__ float wpart[1024];

    const int tid = threadIdx.x;
    const int bx  = blockIdx.x;
    const int sp  = bx & 15;
    const int kl  = bx >> 4;
    const int k   = kl >> 3;
    const int l   = kl & 7;

    if (tid < 128)
        chunk[tid] = (tid < 64) ? latent_tokens[(k * 8 + l) * 64 + tid]
                                : token_embeddings[l * 64 + (tid - 64)];
    __syncthreads();

    const float* hWp = (l == 0) ? h_W0 : (h_W + (l - 1) * 128 * 64);
    if (tid < 256) {
        const int q = tid >> 6, j = tid & 63;
        float acc = 0.f;
        #pragma unroll
        for (int i = 0; i < 32; i++) {
            int ii = q * 32 + i;
            acc = fmaf(chunk[ii], __ldg(hWp + ii * 64 + j), acc);
        }
        part[q][j] = acc;
    }
    __syncthreads();
    if (tid < 64) {
        float hb = (l == 0) ? __ldg(h_b0 + tid) : __ldg(h_b + (l - 1) * 64 + tid);
        pre[tid] = part[0][tid] + part[1][tid] + part[2][tid] + part[3][tid] + hb;
    }
    __syncthreads();
    if (tid < 64) {
        float s1 = 0.f, s2 = 0.f;
        #pragma unroll 8
        for (int i = 0; i < 64; i++) { float v = pre[i]; s1 += v; s2 += v * v; }
        float mu   = s1 * (1.f / 64.f);
        float var  = s2 * (1.f / 64.f) - mu * mu;
        float rstd = rsqrtf(var + 1e-6f);
        float ls = (l == 0) ? __ldg(h_ln_s0 + tid) : __ldg(h_ln_s + (l - 1) * 64 + tid);
        float lb = (l == 0) ? __ldg(h_ln_b0 + tid) : __ldg(h_ln_b + (l - 1) * 64 + tid);
        float h  = fmaf((pre[tid] - mu) * rstd, ls, lb);
        hbuf[tid] = fmaxf(h, 0.f);
    }
    __syncthreads();

    const int OUT  = (l == 0) ? 8064 : 4096;
    const int CH   = OUT >> 4;
    const int o0   = sp * CH, oend = o0 + CH;
    const float* wWp = (l == 0) ? w_W0 : (w_W + (l - 1) * 64 * 4096);
    const float* wbp = (l == 0) ? w_b0 : (w_b + (l - 1) * 4096);

    const int g  = tid >> 8;
    const int tt = tid & 255;

    float acc[2];
    #pragma unroll
    for (int i = 0; i < 2; i++) {
        int o = o0 + tt + i * 256;
        acc[i] = (o < oend && g == 0) ? __ldg(wbp + o) : 0.f;
    }
    const int j0 = g * 32;
    #pragma unroll 8
    for (int jj = 0; jj < 32; jj++) {
        float hj = hbuf[j0 + jj];
        const float* row = wWp + (j0 + jj) * OUT;
        #pragma unroll
        for (int i = 0; i < 2; i++) {
            int o = o0 + tt + i * 256;
            if (o < oend) acc[i] = fmaf(hj, __ldg(row + o), acc[i]);
        }
    }
    wpart[g * 512 + tt]       = acc[0];
    wpart[g * 512 + 256 + tt] = acc[1];
    __syncthreads();

    if (g == 0) {
        #pragma unroll
        for (int i = 0; i < 2; i++) {
            int o = o0 + tt + i * 256;
            if (o < oend) {
                float v = acc[i] + wpart[512 + i * 256 + tt];
                int n, m;
                if (l == 0) { n = o / 126; m = o - n * 126; }
                else        { n = o >> 6;  m = o & 63; }
                int kt = m >> 3, kk = m & 7;
                int nt = n >> 3, nn = n & 7;
                int lane = nn * 4 + (kk & 3);
                int slot = kk >> 2;
                int idx  = (kt * 8 + nt) * 64 + lane * 2 + slot;
                if (l == 0) g_W0u[k * 8192 + idx] = tf32c(v);
                else        g_Wlu[k * 28672 + (l - 1) * 4096 + idx] = tf32c(v);
            }
        }
    }

    if (sp == 0) {
        if (l == 0 && tid < 128) {        // zero-pad m = 126,127 for all n
            int n = tid & 63, m = 126 + (tid >> 6);
            int kt = m >> 3, kk = m & 7;
            int nt = n >> 3, nn = n & 7;
            int idx = (kt * 8 + nt) * 64 + (nn * 4 + (kk & 3)) * 2 + (kk >> 2);
            g_W0u[k * 8192 + idx] = 0u;
        }
        if (tid < 64) {
            const float* bWp = (l == 0) ? bb_W0 : (bb_W + (l - 1) * 64 * 64);
            float accb = (l == 0) ? __ldg(bb_b0 + tid) : __ldg(bb_b + (l - 1) * 64 + tid);
            #pragma unroll 8
            for (int j = 0; j < 64; j++)
                accb = fmaf(hbuf[j], __ldg(bWp + j * 64 + tid), accb);
            g_b[(k * 8 + l) * 64 + tid] = accb;
        }
    }
}

// ---------------------------------------------------------------------------
// Float-only accurate sin: 2-term Cody-Waite reduction by pi, then sinf.
// ---------------------------------------------------------------------------
__device__ __forceinline__ float acc_sin(float x)
{
    float q = rintf(x * 0.318309886183790672f);
    float r = fmaf(-q, 3.14159274101257324f, x);
    r = fmaf(-q, -8.74227800037e-8f, r);
    float s = sinf(r);
    return (((int)q) & 1) ? -s : s;
}

#define MMA_TF32(C, AV, BV) \
    asm volatile("mma.sync.aligned.m16n8k8.row.col.f32.tf32.tf32.f32 " \
        "{%0,%1,%2,%3}, {%4,%5,%6,%7}, {%8,%9}, {%0,%1,%2,%3};" \
        : "+f"((C)[0]), "+f"((C)[1]), "+f"((C)[2]), "+f"((C)[3]) \
        : "r"((AV).x), "r"((AV).y), "r"((AV).z), "r"((AV).w), \
          "r"((BV).x), "r"((BV).y))

#define TILE_BAR(T) asm volatile("bar.sync %0, 128;" :: "r"((T) + 1) : "memory")

// ---------------------------------------------------------------------------
// Kernel 2: tensor-core decoder, 4-way n-split.
// 128 blocks x 512 threads, 64 points/block. Warp (t = wid&3, ns = wid>>2):
// A-tile t (points 16t..16t+15), n-tiles {2ns, 2ns+1}. Tile-local named
// barriers; LN + rgb finalize via smem float4 partial exchange.
// ---------------------------------------------------------------------------
__global__ void __launch_bounds__(512, 1) decode_kernel(
    const float* __restrict__ rays,
    const float* __restrict__ ln_s0, const float* __restrict__ ln_b0,
    const float* __restrict__ ln_s,  const float* __restrict__ ln_b,
    const float* __restrict__ rgb_W, const float* __restrict__ rgb_b,
    float* __restrict__ out)
{
    extern __shared__ u32 smem_u[];
    u32*    sW    = smem_u;                       // 36864 u32 (147456 B)
    u32*    sA    = smem_u + 36864;               // 8192 u32 (4 tiles x 2048)
    float*  sBias = (float*)(smem_u + 45056);     // 512
    float*  sLN   = (float*)(smem_u + 45568);     // 1024
    float4* sRed  = (float4*)(smem_u + 46592);    // 64 pts x 4 ns  (4096 B)
    float4* sRGB  = (float4*)(smem_u + 47616);    // 64 pts x 4 ns  (4096 B)

    const int tid  = threadIdx.x;
    const int wid  = tid >> 5;
    const int lane = tid & 31;
    const int t    = wid & 3;       // A-tile
    const int ns   = wid >> 2;      // n-split 0..3 (n-tiles 2ns, 2ns+1)
    const int gid  = lane >> 2;     // row group 0..7
    const int tig  = lane & 3;      // thread in group
    const int k    = blockIdx.x >> 6;
    const int bx   = blockIdx.x;

    // ---- stage weights (frag layout preserved) ----
    {
        const uint4* s0 = (const uint4*)(g_W0u + k * 8192);     // 2048 uint4
        const uint4* s1 = (const uint4*)(g_Wlu + k * 28672);    // 7168 uint4
        #pragma unroll
        for (int i = 0; i < 4; i++)  ((uint4*)sW)[tid + i * 512] = __ldg(s0 + tid + i * 512);
        #pragma unroll
        for (int i = 0; i < 14; i++) ((uint4*)(sW + 8192))[tid + i * 512] = __ldg(s1 + tid + i * 512);
    }
    // ---- stage biases + LN params ----
    if (tid < 512) sBias[tid] = __ldg(g_b + k * 512 + tid);
    #pragma unroll
    for (int i = tid; i < 1024; i += 512) {
        int l = i >> 7, j = i & 127;
        float v;
        if (l == 0) v = (j < 64) ? __ldg(ln_s0 + j) : __ldg(ln_b0 + j - 64);
        else        v = (j < 64) ? __ldg(ln_s + (l - 1) * 64 + j)
                                 : __ldg(ln_b + (l - 1) * 64 + j - 64);
        sLN[i] = v;
    }

    // ---- positional encoding into A-fragment layout (8 lanes/point) ----
    {
        const int pb = tid >> 3;            // point in block 0..63
        const int s  = tid & 7;
        const int pl = pb & 15;
        u32* Ar = sA + (pb >> 4) * 2048;
        const float* r = rays + (bx * 64 + pb) * 6;
        float ox = __ldg(r + 0), oy = __ldg(r + 1), oz = __ldg(r + 2);
        float dx = __ldg(r + 3), dy = __ldg(r + 4), dz = __ldg(r + 5);
        float pv[6];
        pv[0] = dx; pv[1] = dy; pv[2] = dz;
        pv[3] = oy * dz - oz * dy;
        pv[4] = oz * dx - ox * dz;
        pv[5] = ox * dy - oy * dx;
        auto sta = [&](int m, float v) {
            int kt = m >> 3, c = m & 7;
            int ln = (pl & 7) * 4 + (c & 3);
            int sl = (pl >> 3) + 2 * (c >> 2);
            Ar[kt * 128 + ln * 4 + sl] = tf32c(v);
        };
        if (s == 6) {
            #pragma unroll
            for (int cm = 0; cm < 6; cm++) sta(cm, pv[cm]);
        }
        if (s == 7) { sta(126, 0.f); sta(127, 0.f); }
        const float PIH = 1.57079632679489662f;
        for (int f = s; f < 10; f += 8) {
            float fr = (float)(1 << f);
            #pragma unroll
            for (int cm = 0; cm < 6; cm++) {
                float a = pv[cm] * fr;
                sta(6 + f * 6 + cm, acc_sin(a));
                sta(66 + f * 6 + cm, acc_sin(a + PIH));
            }
        }
    }
    __syncthreads();          // the ONLY block-wide barrier

    u32* At = sA + t * 2048;
    const int nt0 = 2 * ns;               // this warp's n-tiles
    const int pb0 = t * 16 + gid;         // this thread's two points: pb0, pb0+8

    float C[2][4];
    float y[2][4];                        // kept past mma for rgb head

    #pragma unroll 1
    for (int l = 0; l < 8; l++) {
        const u32* Wl = (l == 0) ? sW : (sW + 8192 + (l - 1) * 4096);
        const int KT = (l == 0) ? 16 : 8;

        #pragma unroll
        for (int q = 0; q < 2; q++) {
            int n0 = (nt0 + q) * 8 + 2 * tig;
            float b0v = sBias[l * 64 + n0];
            float b1v = sBias[l * 64 + n0 + 1];
            C[q][0] = b0v; C[q][1] = b1v;
            C[q][2] = b0v; C[q][3] = b1v;
        }

        #pragma unroll 8
        for (int kt = 0; kt < KT; kt++) {
            uint4 av = *(const uint4*)(At + kt * 128 + lane * 4);
            uint2 bv0 = *(const uint2*)(Wl + (kt * 8 + nt0)     * 64 + lane * 2);
            uint2 bv1 = *(const uint2*)(Wl + (kt * 8 + nt0 + 1) * 64 + lane * 2);
            MMA_TF32(C[0], av, bv0);
            MMA_TF32(C[1], av, bv1);
        }

        // ---- LN partials: 16 cols per warp -> shuffle in 4-lane group ----
        float s1a = 0.f, s2a = 0.f, s1b = 0.f, s2b = 0.f;
        #pragma unroll
        for (int q = 0; q < 2; q++) {
            s1a += C[q][0] + C[q][1];
            s2a  = fmaf(C[q][0], C[q][0], fmaf(C[q][1], C[q][1], s2a));
            s1b += C[q][2] + C[q][3];
            s2b  = fmaf(C[q][2], C[q][2], fmaf(C[q][3], C[q][3], s2b));
        }
        #pragma unroll
        for (int mm = 1; mm < 4; mm <<= 1) {
            s1a += __shfl_xor_sync(0xffffffffu, s1a, mm, 32);
            s2a += __shfl_xor_sync(0xffffffffu, s2a, mm, 32);
            s1b += __shfl_xor_sync(0xffffffffu, s1b, mm, 32);
            s2b += __shfl_xor_sync(0xffffffffu, s2b, mm, 32);
        }
        if (tig == 0)
            sRed[pb0 * 4 + ns] = make_float4(s1a, s2a, s1b, s2b);
        TILE_BAR(t);

        float S1a = 0.f, S2a = 0.f, S1b = 0.f, S2b = 0.f;
        #pragma unroll
        for (int j = 0; j < 4; j++) {
            float4 v = sRed[pb0 * 4 + j];
            S1a += v.x; S2a += v.y; S1b += v.z; S2b += v.w;
        }
        float mu0 = S1a * (1.f / 64.f);
        float mu1 = S1b * (1.f / 64.f);
        float rs0 = rsqrtf(S2a * (1.f / 64.f) - mu0 * mu0 + 1e-6f);
        float rs1 = rsqrtf(S2b * (1.f / 64.f) - mu1 * mu1 + 1e-6f);

        #pragma unroll
        for (int q = 0; q < 2; q++) {
            int n0 = (nt0 + q) * 8 + 2 * tig;
            float ls0 = sLN[l * 128 + n0],      ls1 = sLN[l * 128 + n0 + 1];
            float lb0 = sLN[l * 128 + 64 + n0], lb1 = sLN[l * 128 + 64 + n0 + 1];
            y[q][0] = fmaxf(fmaf((C[q][0] - mu0) * rs0, ls0, lb0), 0.f);
            y[q][1] = fmaxf(fmaf((C[q][1] - mu0) * rs0, ls1, lb1), 0.f);
            y[q][2] = fmaxf(fmaf((C[q][2] - mu1) * rs1, ls0, lb0), 0.f);
            y[q][3] = fmaxf(fmaf((C[q][3] - mu1) * rs1, ls1, lb1), 0.f);
            if (l < 7) {
                // write next-layer A fragments (k-tile nt0+q, cols n0, n0+1)
                int nt = nt0 + q;
                int c0 = n0 & 7;
                int b0i = nt * 128 + (gid * 4 + (c0 & 3)) * 4 + 2 * (c0 >> 2);
                At[b0i]     = tf32c(y[q][0]);     // row gid
                At[b0i + 1] = tf32c(y[q][2]);     // row gid+8
                int c1 = c0 + 1;
                int b1i = nt * 128 + (gid * 4 + (c1 & 3)) * 4 + 2 * (c1 >> 2);
                At[b1i]     = tf32c(y[q][1]);
                At[b1i + 1] = tf32c(y[q][3]);
            }
        }
        if (l < 7) TILE_BAR(t);
    }

    // ---- rgb head + sigmoid ----
    {
        float r0[3] = {0.f, 0.f, 0.f};
        float r1[3] = {0.f, 0.f, 0.f};
        #pragma unroll
        for (int q = 0; q < 2; q++) {
            int n0 = (nt0 + q) * 8 + 2 * tig;
            #pragma unroll
            for (int ch = 0; ch < 3; ch++) {
                float w0 = __ldg(rgb_W + n0 * 3 + ch);
                float w1 = __ldg(rgb_W + (n0 + 1) * 3 + ch);
                r0[ch] = fmaf(y[q][0], w0, fmaf(y[q][1], w1, r0[ch]));
                r1[ch] = fmaf(y[q][2], w0, fmaf(y[q][3], w1, r1[ch]));
            }
        }
        #pragma unroll
        for (int mm = 1; mm < 4; mm <<= 1) {
            #pragma unroll
            for (int ch = 0; ch < 3; ch++) {
                r0[ch] += __shfl_xor_sync(0xffffffffu, r0[ch], mm, 32);
                r1[ch] += __shfl_xor_sync(0xffffffffu, r1[ch], mm, 32);
            }
        }
        if (tig == 0) {
            sRGB[pb0 * 4 + ns]       = make_float4(r0[0], r0[1], r0[2], 0.f);
            sRGB[(pb0 + 8) * 4 + ns] = make_float4(r1[0], r1[1], r1[2], 0.f);
        }
        TILE_BAR(t);
        if (ns == 0 && lane < 16) {
            int p = t * 16 + lane;
            float4 a0 = sRGB[p * 4 + 0];
            float4 a1 = sRGB[p * 4 + 1];
            float4 a2 = sRGB[p * 4 + 2];
            float4 a3 = sRGB[p * 4 + 3];
            float v0 = a0.x + a1.x + a2.x + a3.x + __ldg(rgb_b + 0);
            float v1 = a0.y + a1.y + a2.y + a3.y + __ldg(rgb_b + 1);
            float v2 = a0.z + a1.z + a2.z + a3.z + __ldg(rgb_b + 2);
            int gp = bx * 64 + p;
            out[gp * 3 + 0] = 1.f / (1.f + expf(-v0));
            out[gp * 3 + 1] = 1.f / (1.f + expf(-v1));
            out[gp * 3 + 2] = 1.f / (1.f + expf(-v2));
        }
    }
}

// ---------------------------------------------------------------------------
extern "C" void kernel_launch(void* const* d_in, const int* in_sizes, int n_in,
                              void* d_out, int out_size)
{
    const float* rays    = (const float*)d_in[0];
    const float* lat     = (const float*)d_in[1];
    const float* temb    = (const float*)d_in[2];
    const float* h_W0    = (const float*)d_in[3];
    const float* h_b0    = (const float*)d_in[4];
    const float* h_ln_s0 = (const float*)d_in[5];
    const float* h_ln_b0 = (const float*)d_in[6];
    const float* w_W0    = (const float*)d_in[7];
    const float* w_b0    = (const float*)d_in[8];
    const float* bb_W0   = (const float*)d_in[9];
    const float* bb_b0   = (const float*)d_in[10];
    const float* ln_s0   = (const float*)d_in[11];
    const float* ln_b0   = (const float*)d_in[12];
    const float* h_W     = (const float*)d_in[13];
    const float* h_b     = (const float*)d_in[14];
    const float* h_ln_s  = (const float*)d_in[15];
    const float* h_ln_b  = (const float*)d_in[16];
    const float* w_W     = (const float*)d_in[17];
    const float* w_b     = (const float*)d_in[18];
    const float* bb_W    = (const float*)d_in[19];
    const float* bb_b    = (const float*)d_in[20];
    const float* ln_s    = (const float*)d_in[21];
    const float* ln_b    = (const float*)d_in[22];
    const float* rgb_W   = (const float*)d_in[23];
    const float* rgb_b   = (const float*)d_in[24];
    float* out = (float*)d_out;

    // 36864 W + 8192 A + 512 bias + 1024 LN + 1024 red + 1024 rgb = 48640 u32
    const int SMEM = 48640 * 4;   // 194560 B
    cudaFuncSetAttribute(decode_kernel,
                         cudaFuncAttributeMaxDynamicSharedMemorySize, SMEM);

    hyper_kernel<<<256, 512>>>(lat, temb, h_W0, h_b0, h_ln_s0, h_ln_b0,
                               w_W0, w_b0, bb_W0, bb_b0,
                               h_W, h_b, h_ln_s, h_ln_b,
                               w_W, w_b, bb_W, bb_b);
    decode_kernel<<<128, 512, SMEM>>>(rays, ln_s0, ln_b0, ln_s, ln_b,
                                      rgb_W, rgb_b, out);
}